// round 2
// baseline (speedup 1.0000x reference)
#include <cuda_runtime.h>
#include <cuda_bf16.h>
#include <math.h>

#define Bb 4
#define Ii 32
#define Nn 4096
#define Dd 64
#define TEM 1.0f
#define WP 0.5f

// padded row stride for SMEM tiles: multiple of 4 floats so float4 loads are
// 16B-aligned for every k (65 was the R1 misaligned-address bug)
#define PAD 68

// ---------------- device scratch (no allocations allowed) ----------------
__device__ int   g_dtype;            // 0=uint8 bool, 1=int32, 2=float32
__device__ int   g_inst[Bb * Nn];    // instance id per (b,n)
__device__ int   g_cnt[Bb * Ii];     // points per (b,i)
__device__ float g_pos[Bb * Nn];     // sum over same-inst cols of (sim-1)^2
__device__ float g_same[Bb * Nn];    // sum over same-inst cols of exp(sim)
__device__ float g_total[Bb * Nn];   // sum over all cols of exp(sim)

// ---------------- kernel 1: detect label dtype + zero counters ----------------
__global__ void detect_kernel(const unsigned int* lab_words) {
    __shared__ int notInt, notFloat;
    int t = threadIdx.x;
    if (t == 0) { notInt = 0; notFloat = 0; }
    __syncthreads();
    int vi = 0, vf = 0;
    for (int i = t; i < 4096; i += blockDim.x) {
        unsigned int w = lab_words[i];
        if (w > 1u) vi = 1;
        if (w != 0u && w != 0x3F800000u) vf = 1;
    }
    if (vi) atomicOr(&notInt, 1);
    if (vf) atomicOr(&notFloat, 1);
    __syncthreads();
    if (t == 0) {
        g_dtype = (!notInt) ? 1 : ((!notFloat) ? 2 : 0);
    }
    if (t < Bb * Ii) g_cnt[t] = 0;
}

// ---------------- kernel 2: instance id per point + counts ----------------
__global__ void inst_kernel(const void* lab) {
    int idx = blockIdx.x * blockDim.x + threadIdx.x;  // over B*N
    if (idx >= Bb * Nn) return;
    int b = idx / Nn;
    int n = idx - b * Nn;
    int dt = g_dtype;
    const unsigned char* l8  = (const unsigned char*)lab;
    const int*           l32 = (const int*)lab;
    const float*         lf  = (const float*)lab;
    int inst = -1;
    #pragma unroll 1
    for (int i = 0; i < Ii; i++) {
        size_t base = ((size_t)b * Ii + i) * Nn + n;
        bool v;
        if (dt == 0)      v = (l8[base] != 0);
        else if (dt == 1) v = (l32[base] != 0);
        else              v = (lf[base] != 0.0f);
        if (v) { inst = i; break; }
    }
    g_inst[idx] = inst;
    if (inst >= 0) atomicAdd(&g_cnt[b * Ii + inst], 1);
}

// ---------------- kernel 3: tiled X·X^T with fused epilogue ----------------
// grid: B * (N/64) blocks, 256 threads (16x16), each block: 64 rows x full N
__global__ __launch_bounds__(256) void sim_kernel(const float* __restrict__ x) {
    __shared__ float As[Dd][PAD];  // As[k][p_local]
    __shared__ float Bs[Dd][PAD];  // Bs[k][n_local]

    int blk = blockIdx.x;
    int b   = blk >> 6;          // N/64 == 64 tiles per batch
    int rt  = blk & 63;
    int p0  = rt * 64;

    int tid = threadIdx.x;
    int tx  = tid & 15;
    int ty  = tid >> 4;

    const float* xb = x + (size_t)b * Nn * Dd;

    // load A tile (64 rows x 64 dims), transposed into As[k][p]
    #pragma unroll
    for (int j = 0; j < 16; j++) {
        int e = tid + 256 * j;
        int p = e >> 6;
        int k = e & 63;
        As[k][p] = xb[(size_t)(p0 + p) * Dd + k];
    }

    // my 4 rows: p_local = ty*4 + i
    int4 ip4 = *(const int4*)&g_inst[b * Nn + p0 + ty * 4];
    int ip[4] = { ip4.x, ip4.y, ip4.z, ip4.w };

    float te[4] = {0.f, 0.f, 0.f, 0.f};
    float se[4] = {0.f, 0.f, 0.f, 0.f};
    float ps[4] = {0.f, 0.f, 0.f, 0.f};

    for (int c = 0; c < Nn / 64; c++) {
        __syncthreads();  // previous tile's compute done before overwriting Bs
        #pragma unroll
        for (int j = 0; j < 16; j++) {
            int e = tid + 256 * j;
            int n = e >> 6;
            int k = e & 63;
            Bs[k][n] = xb[(size_t)(c * 64 + n) * Dd + k];
        }
        __syncthreads();

        float acc[4][4];
        #pragma unroll
        for (int i = 0; i < 4; i++)
            #pragma unroll
            for (int j = 0; j < 4; j++) acc[i][j] = 0.f;

        #pragma unroll 8
        for (int k = 0; k < Dd; k++) {
            float4 a  = *(const float4*)&As[k][ty * 4];
            float4 bq = *(const float4*)&Bs[k][tx * 4];
            float av[4] = { a.x, a.y, a.z, a.w };
            float bv[4] = { bq.x, bq.y, bq.z, bq.w };
            #pragma unroll
            for (int i = 0; i < 4; i++)
                #pragma unroll
                for (int j = 0; j < 4; j++)
                    acc[i][j] = fmaf(av[i], bv[j], acc[i][j]);
        }

        // epilogue: exp + masked accumulations
        int4 in4 = *(const int4*)&g_inst[b * Nn + c * 64 + tx * 4];
        int in_[4] = { in4.x, in4.y, in4.z, in4.w };
        #pragma unroll
        for (int i = 0; i < 4; i++) {
            #pragma unroll
            for (int j = 0; j < 4; j++) {
                float s = acc[i][j];
                float e = __expf(s);   // TEM == 1.0
                te[i] += e;
                if (in_[j] == ip[i]) {
                    se[i] += e;
                    float d = s - 1.0f;
                    ps[i] += d * d;
                }
            }
        }
    }

    // reduce across the 16 threads (tx) sharing each row
    #pragma unroll
    for (int i = 0; i < 4; i++) {
        #pragma unroll
        for (int off = 8; off > 0; off >>= 1) {
            te[i] += __shfl_down_sync(0xffffffffu, te[i], off, 16);
            se[i] += __shfl_down_sync(0xffffffffu, se[i], off, 16);
            ps[i] += __shfl_down_sync(0xffffffffu, ps[i], off, 16);
        }
        if (tx == 0) {
            int p = p0 + ty * 4 + i;
            size_t o = (size_t)b * Nn + p;
            g_total[o] = te[i];
            g_same[o]  = se[i];
            g_pos[o]   = ps[i];
        }
    }
}

// ---------------- kernel 4: per-instance reduce -> scalar ----------------
__global__ void final_kernel(float* out) {
    __shared__ float s_lp[Bb * Ii];
    __shared__ float s_ln[Bb * Ii];
    __shared__ float s_red[256];
    int t = threadIdx.x;
    if (t < Bb * Ii) { s_lp[t] = 0.f; s_ln[t] = 0.f; }
    __syncthreads();

    for (int idx = t; idx < Bb * Nn; idx += blockDim.x) {
        int b = idx >> 12;  // N = 4096
        int i = g_inst[idx];
        if (i >= 0) {
            atomicAdd(&s_lp[b * Ii + i], g_pos[idx]);
            float neg = g_total[idx] - g_same[idx];
            atomicAdd(&s_ln[b * Ii + i], logf(fmaxf(neg, 1e-30f)));
        }
    }
    __syncthreads();

    float contrib = 0.f;
    if (t < Bb * Ii) {
        float cnt = (float)g_cnt[t];
        float valid = (cnt >= 5.0f) ? 1.0f : 0.0f;
        float lp = s_lp[t] / fmaxf(cnt * cnt, 1.0f);
        float ln = s_ln[t] / fmaxf(cnt, 1.0f);
        contrib = valid * (WP * lp + (1.0f - WP) * ln);
    }
    s_red[t] = contrib;
    __syncthreads();
    for (int off = 128; off > 0; off >>= 1) {
        if (t < off) s_red[t] += s_red[t + off];
        __syncthreads();
    }
    if (t == 0) out[0] = s_red[0] / (float)(Bb * Ii);
}

// ---------------- launch ----------------
extern "C" void kernel_launch(void* const* d_in, const int* in_sizes, int n_in,
                              void* d_out, int out_size) {
    const float* x   = (const float*)d_in[0];
    const void*  lab = d_in[1];
    float* out = (float*)d_out;

    detect_kernel<<<1, 256>>>((const unsigned int*)lab);
    inst_kernel<<<(Bb * Nn + 255) / 256, 256>>>(lab);
    sim_kernel<<<Bb * (Nn / 64), 256>>>(x);
    final_kernel<<<1, 256>>>(out);
}

// round 3
// speedup vs baseline: 1.3002x; 1.3002x over previous
#include <cuda_runtime.h>
#include <cuda_bf16.h>
#include <math.h>

#define Bb 4
#define Ii 32
#define Nn 4096
#define Dd 64
#define TEM 1.0f
#define WP 0.5f
#define PAD 68   // row stride (floats), multiple of 4 -> 16B-aligned float4 rows

// ---------------- device scratch (no allocations allowed) ----------------
__device__ int   g_dtype;            // 0=uint8 bool, 1=int32, 2=float32
__device__ int   g_inst[Bb * Nn];    // instance id per (b,n)
__device__ int   g_cnt[Bb * Ii];     // points per (b,i)
__device__ float g_lp[Bb * Ii];      // sum over rows of (sim-1)^2 masked
__device__ float g_ln[Bb * Ii];      // sum over rows of log(neg-sum)

// packed f32x2 fma: d = a*b + c (lane-wise on two packed floats)
__device__ __forceinline__ unsigned long long ffma2(unsigned long long a,
                                                    unsigned long long b,
                                                    unsigned long long c) {
    unsigned long long d;
    asm("fma.rn.f32x2 %0, %1, %2, %3;" : "=l"(d) : "l"(a), "l"(b), "l"(c));
    return d;
}
__device__ __forceinline__ unsigned long long dup2(float v) {
    unsigned long long d;
    asm("mov.b64 %0, {%1, %1};" : "=l"(d) : "f"(v));
    return d;
}
__device__ __forceinline__ void unpack2(unsigned long long v, float& lo, float& hi) {
    asm("mov.b64 {%0, %1}, %2;" : "=f"(lo), "=f"(hi) : "l"(v));
}

// ---------------- kernel 1: detect label dtype + zero accumulators ----------------
__global__ void detect_kernel(const unsigned int* lab_words) {
    __shared__ int notInt, notFloat;
    int t = threadIdx.x;
    if (t == 0) { notInt = 0; notFloat = 0; }
    __syncthreads();
    int vi = 0, vf = 0;
    for (int i = t; i < 4096; i += blockDim.x) {
        unsigned int w = lab_words[i];
        if (w > 1u) vi = 1;
        if (w != 0u && w != 0x3F800000u) vf = 1;
    }
    if (vi) atomicOr(&notInt, 1);
    if (vf) atomicOr(&notFloat, 1);
    __syncthreads();
    if (t == 0) g_dtype = (!notInt) ? 1 : ((!notFloat) ? 2 : 0);
    if (t < Bb * Ii) { g_cnt[t] = 0; g_lp[t] = 0.f; g_ln[t] = 0.f; }
}

// ---------------- kernel 2: instance id per point + counts ----------------
__global__ void inst_kernel(const void* lab) {
    int idx = blockIdx.x * blockDim.x + threadIdx.x;  // over B*N
    if (idx >= Bb * Nn) return;
    int b = idx / Nn;
    int n = idx - b * Nn;
    int dt = g_dtype;
    const unsigned char* l8  = (const unsigned char*)lab;
    const int*           l32 = (const int*)lab;
    const float*         lf  = (const float*)lab;
    int inst = -1;
    #pragma unroll 1
    for (int i = 0; i < Ii; i++) {
        size_t base = ((size_t)b * Ii + i) * Nn + n;
        bool v;
        if (dt == 0)      v = (l8[base] != 0);
        else if (dt == 1) v = (l32[base] != 0);
        else              v = (lf[base] != 0.0f);
        if (v) { inst = i; break; }
    }
    g_inst[idx] = inst;
    if (inst >= 0) atomicAdd(&g_cnt[b * Ii + inst], 1);
}

// ---------------- kernel 3: tiled X·X^T, packed f32x2 FMA, fused epilogue ----------------
// grid: B * (N/64) blocks, 256 threads (16x16). Block computes 64 rows x full N.
// Accumulators packed across ROW PAIRS: acc2[i2][j] = sims of rows (2*i2, 2*i2+1), col j.
__global__ __launch_bounds__(256) void sim_kernel(const float* __restrict__ x) {
    __shared__ float As[Dd][PAD];  // As[k][p_local]
    __shared__ float Bs[Dd][PAD];  // Bs[k][n_local]

    int blk = blockIdx.x;
    int b   = blk >> 6;
    int rt  = blk & 63;
    int p0  = rt * 64;

    int tid = threadIdx.x;
    int tx  = tid & 15;
    int ty  = tid >> 4;

    const float* xb = x + (size_t)b * Nn * Dd;

    #pragma unroll
    for (int j = 0; j < 16; j++) {
        int e = tid + 256 * j;
        int p = e >> 6;
        int k = e & 63;
        As[k][p] = xb[(size_t)(p0 + p) * Dd + k];
    }

    int4 ip4 = *(const int4*)&g_inst[b * Nn + p0 + ty * 4];
    int ip[4] = { ip4.x, ip4.y, ip4.z, ip4.w };

    float te[4] = {0.f, 0.f, 0.f, 0.f};
    float se[4] = {0.f, 0.f, 0.f, 0.f};
    float ps[4] = {0.f, 0.f, 0.f, 0.f};

    for (int c = 0; c < Nn / 64; c++) {
        __syncthreads();
        #pragma unroll
        for (int j = 0; j < 16; j++) {
            int e = tid + 256 * j;
            int n = e >> 6;
            int k = e & 63;
            Bs[k][n] = xb[(size_t)(c * 64 + n) * Dd + k];
        }
        __syncthreads();

        unsigned long long acc2[2][4];
        #pragma unroll
        for (int i2 = 0; i2 < 2; i2++)
            #pragma unroll
            for (int j = 0; j < 4; j++) acc2[i2][j] = 0ull;

        #pragma unroll 8
        for (int k = 0; k < Dd; k++) {
            // two row-pairs: (p0,p1),(p2,p3) — contiguous floats reinterpreted as b64
            ulonglong2 av = *(const ulonglong2*)&As[k][ty * 4];
            float4 bq = *(const float4*)&Bs[k][tx * 4];
            unsigned long long b0 = dup2(bq.x);
            unsigned long long b1 = dup2(bq.y);
            unsigned long long b2 = dup2(bq.z);
            unsigned long long b3 = dup2(bq.w);
            acc2[0][0] = ffma2(av.x, b0, acc2[0][0]);
            acc2[0][1] = ffma2(av.x, b1, acc2[0][1]);
            acc2[0][2] = ffma2(av.x, b2, acc2[0][2]);
            acc2[0][3] = ffma2(av.x, b3, acc2[0][3]);
            acc2[1][0] = ffma2(av.y, b0, acc2[1][0]);
            acc2[1][1] = ffma2(av.y, b1, acc2[1][1]);
            acc2[1][2] = ffma2(av.y, b2, acc2[1][2]);
            acc2[1][3] = ffma2(av.y, b3, acc2[1][3]);
        }

        // epilogue: exp + masked accumulations (scalar; ~14% of mainloop instrs)
        int4 in4 = *(const int4*)&g_inst[b * Nn + c * 64 + tx * 4];
        int in_[4] = { in4.x, in4.y, in4.z, in4.w };
        #pragma unroll
        for (int i2 = 0; i2 < 2; i2++) {
            #pragma unroll
            for (int j = 0; j < 4; j++) {
                float slo, shi;
                unpack2(acc2[i2][j], slo, shi);
                int rlo = i2 * 2, rhi = i2 * 2 + 1;
                float elo = __expf(slo);
                float ehi = __expf(shi);
                te[rlo] += elo;
                te[rhi] += ehi;
                if (in_[j] == ip[rlo]) {
                    se[rlo] += elo;
                    float d = slo - 1.0f; ps[rlo] += d * d;
                }
                if (in_[j] == ip[rhi]) {
                    se[rhi] += ehi;
                    float d = shi - 1.0f; ps[rhi] += d * d;
                }
            }
        }
    }

    // reduce across the 16 threads (tx) sharing each row, then fold log into
    // per-instance global accumulators (kills the old 116us final kernel)
    #pragma unroll
    for (int i = 0; i < 4; i++) {
        #pragma unroll
        for (int off = 8; off > 0; off >>= 1) {
            te[i] += __shfl_down_sync(0xffffffffu, te[i], off, 16);
            se[i] += __shfl_down_sync(0xffffffffu, se[i], off, 16);
            ps[i] += __shfl_down_sync(0xffffffffu, ps[i], off, 16);
        }
        if (tx == 0 && ip[i] >= 0) {
            int a = b * Ii + ip[i];
            atomicAdd(&g_lp[a], ps[i]);
            atomicAdd(&g_ln[a], logf(fmaxf(te[i] - se[i], 1e-30f)));
        }
    }
}

// ---------------- kernel 4: tiny per-instance finish -> scalar ----------------
__global__ void final_kernel(float* out) {
    __shared__ float s_red[128];
    int t = threadIdx.x;  // 128 threads, one per (b,i)
    float cnt = (float)g_cnt[t];
    float valid = (cnt >= 5.0f) ? 1.0f : 0.0f;
    float lp = g_lp[t] / fmaxf(cnt * cnt, 1.0f);
    float ln = g_ln[t] / fmaxf(cnt, 1.0f);
    s_red[t] = valid * (WP * lp + (1.0f - WP) * ln);
    __syncthreads();
    for (int off = 64; off > 0; off >>= 1) {
        if (t < off) s_red[t] += s_red[t + off];
        __syncthreads();
    }
    if (t == 0) out[0] = s_red[0] / (float)(Bb * Ii);
}

// ---------------- launch ----------------
extern "C" void kernel_launch(void* const* d_in, const int* in_sizes, int n_in,
                              void* d_out, int out_size) {
    const float* x   = (const float*)d_in[0];
    const void*  lab = d_in[1];
    float* out = (float*)d_out;

    detect_kernel<<<1, 256>>>((const unsigned int*)lab);
    inst_kernel<<<(Bb * Nn + 255) / 256, 256>>>(lab);
    sim_kernel<<<Bb * (Nn / 64), 256>>>(x);
    final_kernel<<<1, 128>>>(out);
}

// round 5
// speedup vs baseline: 1.4630x; 1.1253x over previous
#include <cuda_runtime.h>
#include <cuda_bf16.h>
#include <math.h>

#define Bb 4
#define Ii 32
#define Nn 4096
#define Dd 64
#define TEM 1.0f
#define WP 0.5f

#define TILE 128        // rows & cols per block tile
#define KCH 16          // k-chunk staged for B
#define PADW 132        // padded row stride (floats): mult of 4 -> aligned float4

// ---------------- device scratch (no allocations allowed) ----------------
__device__ int   g_dtype;
__device__ int   g_inst[Bb * Nn];
__device__ int   g_cnt[Bb * Ii];
__device__ float g_lp[Bb * Ii];
__device__ float g_ln[Bb * Ii];

__device__ __forceinline__ unsigned long long ffma2(unsigned long long a,
                                                    unsigned long long b,
                                                    unsigned long long c) {
    unsigned long long d;
    asm("fma.rn.f32x2 %0, %1, %2, %3;" : "=l"(d) : "l"(a), "l"(b), "l"(c));
    return d;
}
__device__ __forceinline__ unsigned long long dup2(float v) {
    unsigned long long d;
    asm("mov.b64 %0, {%1, %1};" : "=l"(d) : "f"(v));
    return d;
}
__device__ __forceinline__ void unpack2(unsigned long long v, float& lo, float& hi) {
    asm("mov.b64 {%0, %1}, %2;" : "=f"(lo), "=f"(hi) : "l"(v));
}

// ---------------- kernel 1: detect label dtype + zero accumulators ----------------
__global__ void detect_kernel(const unsigned int* lab_words) {
    __shared__ int notInt, notFloat;
    int t = threadIdx.x;
    if (t == 0) { notInt = 0; notFloat = 0; }
    __syncthreads();
    int vi = 0, vf = 0;
    for (int i = t; i < 4096; i += blockDim.x) {
        unsigned int w = lab_words[i];
        if (w > 1u) vi = 1;
        if (w != 0u && w != 0x3F800000u) vf = 1;
    }
    if (vi) atomicOr(&notInt, 1);
    if (vf) atomicOr(&notFloat, 1);
    __syncthreads();
    if (t == 0) g_dtype = (!notInt) ? 1 : ((!notFloat) ? 2 : 0);
    if (t < Bb * Ii) { g_cnt[t] = 0; g_lp[t] = 0.f; g_ln[t] = 0.f; }
}

// ---------------- kernel 2: instance id per point + counts ----------------
__global__ void inst_kernel(const void* lab) {
    int idx = blockIdx.x * blockDim.x + threadIdx.x;
    if (idx >= Bb * Nn) return;
    int b = idx / Nn;
    int n = idx - b * Nn;
    int dt = g_dtype;
    const unsigned char* l8  = (const unsigned char*)lab;
    const int*           l32 = (const int*)lab;
    const float*         lf  = (const float*)lab;
    int inst = -1;
    #pragma unroll 1
    for (int i = 0; i < Ii; i++) {
        size_t base = ((size_t)b * Ii + i) * Nn + n;
        bool v;
        if (dt == 0)      v = (l8[base] != 0);
        else if (dt == 1) v = (l32[base] != 0);
        else              v = (lf[base] != 0.0f);
        if (v) { inst = i; break; }
    }
    g_inst[idx] = inst;
    if (inst >= 0) atomicAdd(&g_cnt[b * Ii + inst], 1);
}

// ---------------- kernel 3: 128x128 tiles, 8x8 per-thread, f32x2 FMA ----------------
// grid: B * (N/128) = 128 blocks, 256 threads (16x16).
// Thread (tx,ty): rows ty*8..ty*8+7, cols tx*8..tx*8+7 of the 128x128 tile.
__global__ __launch_bounds__(256, 1) void sim_kernel(const float* __restrict__ x) {
    __shared__ float As[Dd][PADW];   // A tile transposed: As[k][p], staged once
    __shared__ float Bs[KCH][PADW];  // B chunk transposed: Bs[k][n]

    int blk = blockIdx.x;
    int b   = blk >> 5;          // N/128 == 32 tiles per batch
    int rt  = blk & 31;
    int p0  = rt * TILE;

    int tid = threadIdx.x;
    int tx  = tid & 15;
    int ty  = tid >> 4;

    const float* xb = x + (size_t)b * Nn * Dd;

    // stage A tile (128 rows x 64 dims) transposed; one-time, 4-way store conflicts OK
    #pragma unroll
    for (int j = 0; j < 32; j++) {
        int e = tid + 256 * j;
        int p = e >> 6;
        int k = e & 63;
        As[k][p] = xb[(size_t)(p0 + p) * Dd + k];
    }

    // my 8 row instance ids
    int ip[8];
    {
        int4 a = *(const int4*)&g_inst[b * Nn + p0 + ty * 8];
        int4 c = *(const int4*)&g_inst[b * Nn + p0 + ty * 8 + 4];
        ip[0]=a.x; ip[1]=a.y; ip[2]=a.z; ip[3]=a.w;
        ip[4]=c.x; ip[5]=c.y; ip[6]=c.z; ip[7]=c.w;
    }

    float te[8], se[8], ps[8];
    #pragma unroll
    for (int i = 0; i < 8; i++) { te[i]=0.f; se[i]=0.f; ps[i]=0.f; }

    for (int c = 0; c < Nn / TILE; c++) {
        unsigned long long acc2[4][8];
        #pragma unroll
        for (int i2 = 0; i2 < 4; i2++)
            #pragma unroll
            for (int j = 0; j < 8; j++) acc2[i2][j] = 0ull;

        #pragma unroll 1
        for (int kc = 0; kc < Dd / KCH; kc++) {
            __syncthreads();
            // stage B chunk: 128 n x 16 k, transposed into Bs[k][n]
            #pragma unroll
            for (int j = 0; j < 8; j++) {
                int e = tid + 256 * j;
                int k = e & 15;
                int n = e >> 4;
                Bs[k][n] = xb[(size_t)(c * TILE + n) * Dd + kc * KCH + k];
            }
            __syncthreads();

            #pragma unroll
            for (int k = 0; k < KCH; k++) {
                int kk = kc * KCH + k;
                ulonglong2 a01 = *(const ulonglong2*)&As[kk][ty * 8];
                ulonglong2 a23 = *(const ulonglong2*)&As[kk][ty * 8 + 4];
                unsigned long long av[4] = { a01.x, a01.y, a23.x, a23.y };
                float4 b03 = *(const float4*)&Bs[k][tx * 8];
                float4 b47 = *(const float4*)&Bs[k][tx * 8 + 4];
                unsigned long long bv[8];
                bv[0] = dup2(b03.x); bv[1] = dup2(b03.y);
                bv[2] = dup2(b03.z); bv[3] = dup2(b03.w);
                bv[4] = dup2(b47.x); bv[5] = dup2(b47.y);
                bv[6] = dup2(b47.z); bv[7] = dup2(b47.w);
                #pragma unroll
                for (int i2 = 0; i2 < 4; i2++)
                    #pragma unroll
                    for (int j = 0; j < 8; j++)
                        acc2[i2][j] = ffma2(av[i2], bv[j], acc2[i2][j]);
            }
        }

        // epilogue: exp + masked accumulations for this 8x8 sub-tile
        int in_[8];
        {
            int4 a = *(const int4*)&g_inst[b * Nn + c * TILE + tx * 8];
            int4 d = *(const int4*)&g_inst[b * Nn + c * TILE + tx * 8 + 4];
            in_[0]=a.x; in_[1]=a.y; in_[2]=a.z; in_[3]=a.w;
            in_[4]=d.x; in_[5]=d.y; in_[6]=d.z; in_[7]=d.w;
        }
        #pragma unroll
        for (int i2 = 0; i2 < 4; i2++) {
            int rlo = i2 * 2, rhi = i2 * 2 + 1;
            #pragma unroll
            for (int j = 0; j < 8; j++) {
                float slo, shi;
                unpack2(acc2[i2][j], slo, shi);
                float elo = __expf(slo);
                float ehi = __expf(shi);
                te[rlo] += elo;
                te[rhi] += ehi;
                if (in_[j] == ip[rlo]) {
                    se[rlo] += elo;
                    float d = slo - 1.0f; ps[rlo] += d * d;
                }
                if (in_[j] == ip[rhi]) {
                    se[rhi] += ehi;
                    float d = shi - 1.0f; ps[rhi] += d * d;
                }
            }
        }
    }

    // reduce across the 16 tx-threads sharing each row; fold log per instance
    #pragma unroll
    for (int i = 0; i < 8; i++) {
        #pragma unroll
        for (int off = 8; off > 0; off >>= 1) {
            te[i] += __shfl_down_sync(0xffffffffu, te[i], off, 16);
            se[i] += __shfl_down_sync(0xffffffffu, se[i], off, 16);
            ps[i] += __shfl_down_sync(0xffffffffu, ps[i], off, 16);
        }
        if (tx == 0 && ip[i] >= 0) {
            int a = b * Ii + ip[i];
            atomicAdd(&g_lp[a], ps[i]);
            atomicAdd(&g_ln[a], logf(fmaxf(te[i] - se[i], 1e-30f)));
        }
    }
}

// ---------------- kernel 4: tiny per-instance finish -> scalar ----------------
__global__ void final_kernel(float* out) {
    __shared__ float s_red[128];
    int t = threadIdx.x;
    float cnt = (float)g_cnt[t];
    float valid = (cnt >= 5.0f) ? 1.0f : 0.0f;
    float lp = g_lp[t] / fmaxf(cnt * cnt, 1.0f);
    float ln = g_ln[t] / fmaxf(cnt, 1.0f);
    s_red[t] = valid * (WP * lp + (1.0f - WP) * ln);
    __syncthreads();
    for (int off = 64; off > 0; off >>= 1) {
        if (t < off) s_red[t] += s_red[t + off];
        __syncthreads();
    }
    if (t == 0) out[0] = s_red[0] / (float)(Bb * Ii);
}

// ---------------- launch ----------------
extern "C" void kernel_launch(void* const* d_in, const int* in_sizes, int n_in,
                              void* d_out, int out_size) {
    const float* x   = (const float*)d_in[0];
    const void*  lab = d_in[1];
    float* out = (float*)d_out;

    detect_kernel<<<1, 256>>>((const unsigned int*)lab);
    inst_kernel<<<(Bb * Nn + 255) / 256, 256>>>(lab);
    sim_kernel<<<Bb * (Nn / TILE), 256>>>(x);
    final_kernel<<<1, 128>>>(out);
}

// round 7
// speedup vs baseline: 3.6635x; 2.5041x over previous
#include <cuda_runtime.h>
#include <cuda_bf16.h>
#include <cstdint>
#include <math.h>

#define Bb 4
#define Ii 32
#define Nn 4096
#define Dd 64
#define WP 0.5f

#define TILE 128
#define NT (Nn / TILE)          // 32 col tiles
#define STR 68                  // padded SMEM row stride (floats)

// ---------------- device scratch ----------------
__device__ int      g_dtype;
__device__ int      g_inst[Bb * Nn];
__device__ int      g_cnt[Bb * Ii];
__device__ float    g_lp[Bb * Ii];
__device__ float    g_ln[Bb * Ii];
__device__ unsigned g_maskb[Bb * Ii * (Nn / 32)];   // bit-packed label masks

__device__ __forceinline__ float to_tf32(float v) {
    float r;
    asm("cvt.rna.tf32.f32 %0, %1;" : "=f"(r) : "f"(v));
    return r;
}

// m16n8k8 tf32 mma, accumulate in place
__device__ __forceinline__ void mma8(float* d, const uint32_t* a, uint32_t b0, uint32_t b1) {
    asm volatile(
        "mma.sync.aligned.m16n8k8.row.col.f32.tf32.tf32.f32 "
        "{%0,%1,%2,%3}, {%4,%5,%6,%7}, {%8,%9}, {%0,%1,%2,%3};"
        : "+f"(d[0]), "+f"(d[1]), "+f"(d[2]), "+f"(d[3])
        : "r"(a[0]), "r"(a[1]), "r"(a[2]), "r"(a[3]), "r"(b0), "r"(b1));
}

// ---------------- kernel 1: detect label dtype + zero scratch ----------------
__global__ void detect_kernel(const unsigned int* lab_words) {
    __shared__ int notInt, notFloat;
    int t = threadIdx.x;
    if (t == 0) { notInt = 0; notFloat = 0; }
    __syncthreads();
    int vi = 0, vf = 0;
    for (int i = t; i < 4096; i += blockDim.x) {
        unsigned int w = lab_words[i];
        if (w > 1u) vi = 1;
        if (w != 0u && w != 0x3F800000u) vf = 1;
    }
    if (vi) atomicOr(&notInt, 1);
    if (vf) atomicOr(&notFloat, 1);
    __syncthreads();
    if (t == 0) g_dtype = (!notInt) ? 1 : ((!notFloat) ? 2 : 0);
    if (t < Bb * Ii) { g_cnt[t] = 0; g_lp[t] = 0.f; g_ln[t] = 0.f; }
    for (int i = t; i < Bb * Ii * (Nn / 32); i += blockDim.x) g_maskb[i] = 0u;
}

// ---------------- kernel 2: instance ids + counts + bitmask ----------------
__global__ void inst_kernel(const void* lab) {
    int idx = blockIdx.x * blockDim.x + threadIdx.x;
    if (idx >= Bb * Nn) return;
    int b = idx / Nn;
    int n = idx - b * Nn;
    int dt = g_dtype;
    const unsigned char* l8  = (const unsigned char*)lab;
    const int*           l32 = (const int*)lab;
    const float*         lf  = (const float*)lab;
    int inst = -1;
    #pragma unroll 1
    for (int i = 0; i < Ii; i++) {
        size_t base = ((size_t)b * Ii + i) * Nn + n;
        bool v;
        if (dt == 0)      v = (l8[base] != 0);
        else if (dt == 1) v = (l32[base] != 0);
        else              v = (lf[base] != 0.0f);
        if (v) { inst = i; break; }
    }
    g_inst[idx] = inst;
    if (inst >= 0) {
        atomicAdd(&g_cnt[b * Ii + inst], 1);
        atomicOr(&g_maskb[(b * Ii + inst) * (Nn / 32) + (n >> 5)], 1u << (n & 31));
    }
}

// ---------------- kernel 3: tf32 mma.sync sim + fused epilogue ----------------
// 128 blocks x 256 threads (8 warps). Warp w: rows [p0+16w, p0+16w+16) x full N.
__global__ __launch_bounds__(256, 1) void sim_kernel(const float* __restrict__ x) {
    extern __shared__ float smf[];
    float* As = smf;                 // [128][STR]
    float* Bs = smf + TILE * STR;    // [128][STR]

    int tid = threadIdx.x;
    int wid = tid >> 5;
    int lid = tid & 31;
    int g   = lid >> 2;              // groupID 0..7
    int tg  = lid & 3;               // thread-in-group 0..3

    int blk = blockIdx.x;
    int b   = blk >> 5;
    int rt  = blk & 31;
    int p0  = rt * TILE;
    const float* xb = x + (size_t)b * Nn * Dd;

    int ldr = tid >> 4;              // staging: row 0..15 step, cg 0..15
    int cg  = tid & 15;

    // stage A tile (rows p0..p0+127), tf32-rounded
    #pragma unroll
    for (int t = 0; t < 8; t++) {
        int row = ldr + t * 16;
        float4 v = *(const float4*)(xb + (size_t)(p0 + row) * Dd + cg * 4);
        v.x = to_tf32(v.x); v.y = to_tf32(v.y); v.z = to_tf32(v.z); v.w = to_tf32(v.w);
        *(float4*)(As + row * STR + cg * 4) = v;
    }
    // stage B tile 0
    #pragma unroll
    for (int t = 0; t < 8; t++) {
        int row = ldr + t * 16;
        float4 v = *(const float4*)(xb + (size_t)row * Dd + cg * 4);
        v.x = to_tf32(v.x); v.y = to_tf32(v.y); v.z = to_tf32(v.z); v.w = to_tf32(v.w);
        *(float4*)(Bs + row * STR + cg * 4) = v;
    }
    __syncthreads();

    // A fragments: 8 k-steps x 4 regs, register-resident for the whole kernel
    uint32_t af[8][4];
    {
        int r0 = wid * 16 + g;
        #pragma unroll
        for (int kk = 0; kk < 8; kk++) {
            af[kk][0] = __float_as_uint(As[r0 * STR + kk * 8 + tg]);
            af[kk][1] = __float_as_uint(As[(r0 + 8) * STR + kk * 8 + tg]);
            af[kk][2] = __float_as_uint(As[r0 * STR + kk * 8 + tg + 4]);
            af[kk][3] = __float_as_uint(As[(r0 + 8) * STR + kk * 8 + tg + 4]);
        }
    }

    // my two output rows
    int r0g = p0 + wid * 16 + g;
    int ip0 = g_inst[b * Nn + r0g];
    int ip1 = g_inst[b * Nn + r0g + 8];
    int mb0 = (ip0 >= 0) ? (b * Ii + ip0) * (Nn / 32) : -1;
    int mb1 = (ip1 >= 0) ? (b * Ii + ip1) * (Nn / 32) : -1;

    float te0 = 0.f, te1 = 0.f, se0 = 0.f, se1 = 0.f, ps0 = 0.f, ps1 = 0.f;

    for (int c = 0; c < NT; c++) {
        // prefetch next B tile into registers
        float4 pf[8];
        if (c + 1 < NT) {
            const float* src = xb + (size_t)(c + 1) * TILE * Dd;
            #pragma unroll
            for (int t = 0; t < 8; t++)
                pf[t] = *(const float4*)(src + (size_t)(ldr + t * 16) * Dd + cg * 4);
        }

        float acc[16][4];
        #pragma unroll
        for (int nt = 0; nt < 16; nt++)
            #pragma unroll
            for (int j = 0; j < 4; j++) acc[nt][j] = 0.f;

        #pragma unroll
        for (int kk = 0; kk < 8; kk++) {
            #pragma unroll
            for (int nt = 0; nt < 16; nt++) {
                int nb = nt * 8 + g;
                uint32_t b0 = __float_as_uint(Bs[nb * STR + kk * 8 + tg]);
                uint32_t b1 = __float_as_uint(Bs[nb * STR + kk * 8 + tg + 4]);
                mma8(acc[nt], af[kk], b0, b1);
            }
        }

        // masks for this 128-col window (4 words per row)
        unsigned m0[4], m1[4];
        #pragma unroll
        for (int j = 0; j < 4; j++) {
            m0[j] = (mb0 >= 0) ? g_maskb[mb0 + c * 4 + j] : 0u;
            m1[j] = (mb1 >= 0) ? g_maskb[mb1 + c * 4 + j] : 0u;
        }

        #pragma unroll
        for (int nt = 0; nt < 16; nt++) {
            int cb = nt * 8 + 2 * tg;        // col of acc[nt][0]
            int wj = cb >> 5;
            unsigned w0 = m0[wj], w1 = m1[wj];
            int bit0 = cb & 31, bit1 = (cb + 1) & 31;

            float s00 = acc[nt][0], s01 = acc[nt][1];
            float s10 = acc[nt][2], s11 = acc[nt][3];
            float e00 = __expf(s00), e01 = __expf(s01);
            float e10 = __expf(s10), e11 = __expf(s11);
            te0 += e00 + e01;
            te1 += e10 + e11;
            if ((w0 >> bit0) & 1u) { se0 += e00; float d = s00 - 1.f; ps0 = fmaf(d, d, ps0); }
            if ((w0 >> bit1) & 1u) { se0 += e01; float d = s01 - 1.f; ps0 = fmaf(d, d, ps0); }
            if ((w1 >> bit0) & 1u) { se1 += e10; float d = s10 - 1.f; ps1 = fmaf(d, d, ps1); }
            if ((w1 >> bit1) & 1u) { se1 += e11; float d = s11 - 1.f; ps1 = fmaf(d, d, ps1); }
        }

        __syncthreads();    // everyone done reading Bs
        if (c + 1 < NT) {
            #pragma unroll
            for (int t = 0; t < 8; t++) {
                float4 v = pf[t];
                v.x = to_tf32(v.x); v.y = to_tf32(v.y); v.z = to_tf32(v.z); v.w = to_tf32(v.w);
                *(float4*)(Bs + (ldr + t * 16) * STR + cg * 4) = v;
            }
            __syncthreads();  // Bs ready
        }
    }

    // reduce over the 4 tg-lanes sharing each (row pair)
    #pragma unroll
    for (int off = 2; off > 0; off >>= 1) {
        te0 += __shfl_down_sync(0xffffffffu, te0, off, 4);
        te1 += __shfl_down_sync(0xffffffffu, te1, off, 4);
        se0 += __shfl_down_sync(0xffffffffu, se0, off, 4);
        se1 += __shfl_down_sync(0xffffffffu, se1, off, 4);
        ps0 += __shfl_down_sync(0xffffffffu, ps0, off, 4);
        ps1 += __shfl_down_sync(0xffffffffu, ps1, off, 4);
    }
    if (tg == 0) {
        if (ip0 >= 0) {
            int a = b * Ii + ip0;
            atomicAdd(&g_lp[a], ps0);
            atomicAdd(&g_ln[a], logf(fmaxf(te0 - se0, 1e-30f)));
        }
        if (ip1 >= 0) {
            int a = b * Ii + ip1;
            atomicAdd(&g_lp[a], ps1);
            atomicAdd(&g_ln[a], logf(fmaxf(te1 - se1, 1e-30f)));
        }
    }
}

// ---------------- kernel 4: tiny finish ----------------
__global__ void final_kernel(float* out) {
    __shared__ float s_red[128];
    int t = threadIdx.x;
    float cnt = (float)g_cnt[t];
    float valid = (cnt >= 5.0f) ? 1.0f : 0.0f;
    float lp = g_lp[t] / fmaxf(cnt * cnt, 1.0f);
    float ln = g_ln[t] / fmaxf(cnt, 1.0f);
    s_red[t] = valid * (WP * lp + (1.0f - WP) * ln);
    __syncthreads();
    for (int off = 64; off > 0; off >>= 1) {
        if (t < off) s_red[t] += s_red[t + off];
        __syncthreads();
    }
    if (t == 0) out[0] = s_red[0] / (float)(Bb * Ii);
}

// ---------------- launch ----------------
#define SM_TOTAL (2 * TILE * STR * 4)

extern "C" void kernel_launch(void* const* d_in, const int* in_sizes, int n_in,
                              void* d_out, int out_size) {
    const float* x   = (const float*)d_in[0];
    const void*  lab = d_in[1];
    float* out = (float*)d_out;

    static int configured = 0;
    if (!configured) {
        cudaFuncSetAttribute(sim_kernel, cudaFuncAttributeMaxDynamicSharedMemorySize, SM_TOTAL);
        configured = 1;
    }

    detect_kernel<<<1, 256>>>((const unsigned int*)lab);
    inst_kernel<<<(Bb * Nn + 255) / 256, 256>>>(lab);
    sim_kernel<<<Bb * (Nn / TILE), 256, SM_TOTAL>>>(x);
    final_kernel<<<1, 128>>>(out);
}

// round 9
// speedup vs baseline: 4.1360x; 1.1290x over previous
#include <cuda_runtime.h>
#include <cuda_bf16.h>
#include <cstdint>
#include <math.h>

#define Bb 4
#define Ii 32
#define Nn 4096
#define Dd 64
#define WP 0.5f

#define STR 68          // padded SMEM row stride (floats)
#define CQS 8           // column splits per row band
#define CT_PER 8        // 64-col tiles per block (512 cols / 64)

// ---------------- device scratch ----------------
__device__ int      g_dtype;
__device__ int      g_inst[Bb * Nn];
__device__ int      g_cnt[Bb * Ii];
__device__ float    g_lp[Bb * Ii];
__device__ float    g_ln[Bb * Ii];
__device__ unsigned g_maskb[Bb * Ii * (Nn / 32)];
__device__ float    g_xtf[Bb * Nn * Dd];     // tf32-rounded copy of x (4 MB)
__device__ float    g_te[Bb * Nn];
__device__ float    g_se[Bb * Nn];
__device__ float    g_ps[Bb * Nn];

__device__ __forceinline__ float to_tf32(float v) {
    float r;
    asm("cvt.rna.tf32.f32 %0, %1;" : "=f"(r) : "f"(v));
    return r;
}
__device__ __forceinline__ void mma8(float* d, const uint32_t* a, uint32_t b0, uint32_t b1) {
    asm volatile(
        "mma.sync.aligned.m16n8k8.row.col.f32.tf32.tf32.f32 "
        "{%0,%1,%2,%3}, {%4,%5,%6,%7}, {%8,%9}, {%0,%1,%2,%3};"
        : "+f"(d[0]), "+f"(d[1]), "+f"(d[2]), "+f"(d[3])
        : "r"(a[0]), "r"(a[1]), "r"(a[2]), "r"(a[3]), "r"(b0), "r"(b1));
}
__device__ __forceinline__ uint32_t smem_u32(const void* p) {
    return (uint32_t)__cvta_generic_to_shared(p);
}
__device__ __forceinline__ void cpasync16(uint32_t dst, const float* src) {
    asm volatile("cp.async.cg.shared.global [%0], [%1], 16;" :: "r"(dst), "l"(src));
}
#define CP_COMMIT() asm volatile("cp.async.commit_group;" ::: "memory")
#define CP_WAIT1()  asm volatile("cp.async.wait_group 1;" ::: "memory")
#define CP_WAIT0()  asm volatile("cp.async.wait_group 0;" ::: "memory")

// ---------------- kernel 1: detect label dtype + zero small scratch ----------------
__global__ void detect_kernel(const unsigned int* lab_words) {
    __shared__ int notInt, notFloat;
    int t = threadIdx.x;
    if (t == 0) { notInt = 0; notFloat = 0; }
    __syncthreads();
    int vi = 0, vf = 0;
    for (int i = t; i < 4096; i += blockDim.x) {
        unsigned int w = lab_words[i];
        if (w > 1u) vi = 1;
        if (w != 0u && w != 0x3F800000u) vf = 1;
    }
    if (vi) atomicOr(&notInt, 1);
    if (vf) atomicOr(&notFloat, 1);
    __syncthreads();
    if (t == 0) g_dtype = (!notInt) ? 1 : ((!notFloat) ? 2 : 0);
    if (t < Bb * Ii) { g_cnt[t] = 0; g_lp[t] = 0.f; g_ln[t] = 0.f; }
    for (int i = t; i < Bb * Ii * (Nn / 32); i += blockDim.x) g_maskb[i] = 0u;
}

// ---------------- kernel 2: instance ids + counts + bitmask ----------------
__global__ void inst_kernel(const void* lab) {
    int idx = blockIdx.x * blockDim.x + threadIdx.x;
    if (idx >= Bb * Nn) return;
    int b = idx / Nn;
    int n = idx - b * Nn;
    int dt = g_dtype;
    const unsigned char* l8  = (const unsigned char*)lab;
    const int*           l32 = (const int*)lab;
    const float*         lf  = (const float*)lab;
    int inst = -1;
    #pragma unroll 1
    for (int i = 0; i < Ii; i++) {
        size_t base = ((size_t)b * Ii + i) * Nn + n;
        bool v;
        if (dt == 0)      v = (l8[base] != 0);
        else if (dt == 1) v = (l32[base] != 0);
        else              v = (lf[base] != 0.0f);
        if (v) { inst = i; break; }
    }
    g_inst[idx] = inst;
    if (inst >= 0) {
        atomicAdd(&g_cnt[b * Ii + inst], 1);
        atomicOr(&g_maskb[(b * Ii + inst) * (Nn / 32) + (n >> 5)], 1u << (n & 31));
    }
}

// ---------------- kernel 2b: tf32 round x + zero row stats ----------------
__global__ void cvt_kernel(const float* __restrict__ x) {
    int t = blockIdx.x * blockDim.x + threadIdx.x;
    int stride = gridDim.x * blockDim.x;
    for (int i = t; i < Bb * Nn * Dd; i += stride) g_xtf[i] = to_tf32(x[i]);
    if (t < Bb * Nn) { g_te[t] = 0.f; g_se[t] = 0.f; g_ps[t] = 0.f; }
}

// ---------------- kernel 3: tf32 mma sim, 1024 blocks, cp.async pipeline ----------------
// block: 128 rows (rt) x 512 cols (cq). 8 warps x 16 rows.
__global__ __launch_bounds__(256, 2) void sim_kernel() {
    __shared__ float Bs[2][64 * STR];   // 34816 bytes

    int tid = threadIdx.x;
    int wid = tid >> 5;
    int lid = tid & 31;
    int g   = lid >> 2;
    int tg  = lid & 3;

    int blk = blockIdx.x;
    int b   = blk >> 8;
    int r   = blk & 255;
    int rt  = r >> 3;
    int cq  = r & 7;
    int p0  = rt * 128;
    int c0  = cq * 512;
    const float* xb = g_xtf + (size_t)b * Nn * Dd;

    int ldr = tid >> 4;      // 0..15
    int cg  = tid & 15;

    // stage A (128 rows) through the two B buffers, extract register fragments
    #pragma unroll
    for (int h = 0; h < 2; h++)
        #pragma unroll
        for (int t = 0; t < 4; t++) {
            int row = ldr + t * 16;
            float4 v = *(const float4*)(xb + (size_t)(p0 + h * 64 + row) * Dd + cg * 4);
            *(float4*)(&Bs[h][row * STR + cg * 4]) = v;
        }
    __syncthreads();

    uint32_t af[8][4];
    {
        const float* Ab = Bs[wid >> 2];
        int rc = (wid & 3) * 16 + g;
        #pragma unroll
        for (int kk = 0; kk < 8; kk++) {
            af[kk][0] = __float_as_uint(Ab[rc * STR + kk * 8 + tg]);
            af[kk][1] = __float_as_uint(Ab[(rc + 8) * STR + kk * 8 + tg]);
            af[kk][2] = __float_as_uint(Ab[rc * STR + kk * 8 + tg + 4]);
            af[kk][3] = __float_as_uint(Ab[(rc + 8) * STR + kk * 8 + tg + 4]);
        }
    }
    __syncthreads();   // A reads done; buffers free for B pipeline

    int r0g = p0 + wid * 16 + g;
    int ip0 = g_inst[b * Nn + r0g];
    int ip1 = g_inst[b * Nn + r0g + 8];
    int mb0 = (ip0 >= 0) ? (b * Ii + ip0) * (Nn / 32) : -1;
    int mb1 = (ip1 >= 0) ? (b * Ii + ip1) * (Nn / 32) : -1;

    uint32_t bsm[2] = { smem_u32(&Bs[0][0]), smem_u32(&Bs[1][0]) };
    uint32_t dsto = (uint32_t)(ldr * STR + cg * 4) * 4u;

    // issue tiles 0 and 1
    #pragma unroll
    for (int pre = 0; pre < 2; pre++) {
        const float* src = xb + (size_t)(c0 + pre * 64) * Dd;
        #pragma unroll
        for (int t = 0; t < 4; t++)
            cpasync16(bsm[pre] + dsto + t * 16 * STR * 4, src + (size_t)(ldr + t * 16) * Dd + cg * 4);
        CP_COMMIT();
    }

    float te0 = 0.f, te1 = 0.f, se0 = 0.f, se1 = 0.f, ps0 = 0.f, ps1 = 0.f;

    #pragma unroll 1
    for (int ct = 0; ct < CT_PER; ct++) {
        int buf = ct & 1;
        if (ct == CT_PER - 1) CP_WAIT0(); else CP_WAIT1();
        __syncthreads();

        float acc[8][4];
        #pragma unroll
        for (int nt = 0; nt < 8; nt++)
            #pragma unroll
            for (int j = 0; j < 4; j++) acc[nt][j] = 0.f;

        const float* Bp = Bs[buf];
        #pragma unroll
        for (int kk = 0; kk < 8; kk++) {
            #pragma unroll
            for (int nt = 0; nt < 8; nt++) {
                int nb = nt * 8 + g;
                uint32_t b0 = __float_as_uint(Bp[nb * STR + kk * 8 + tg]);
                uint32_t b1 = __float_as_uint(Bp[nb * STR + kk * 8 + tg + 4]);
                mma8(acc[nt], af[kk], b0, b1);
            }
        }

        // masks for this 64-col window
        int wbase = cq * 16 + ct * 2;
        unsigned m0[2], m1[2];
        #pragma unroll
        for (int j = 0; j < 2; j++) {
            m0[j] = (mb0 >= 0) ? g_maskb[mb0 + wbase + j] : 0u;
            m1[j] = (mb1 >= 0) ? g_maskb[mb1 + wbase + j] : 0u;
        }

        #pragma unroll
        for (int nt = 0; nt < 8; nt++) {
            int cb = nt * 8 + 2 * tg;
            int wj = cb >> 5;
            unsigned w0 = m0[wj], w1 = m1[wj];
            int bit0 = cb & 31, bit1 = (cb + 1) & 31;
            float s00 = acc[nt][0], s01 = acc[nt][1];
            float s10 = acc[nt][2], s11 = acc[nt][3];
            float e00 = __expf(s00), e01 = __expf(s01);
            float e10 = __expf(s10), e11 = __expf(s11);
            te0 += e00 + e01;
            te1 += e10 + e11;
            if ((w0 >> bit0) & 1u) { se0 += e00; float d = s00 - 1.f; ps0 = fmaf(d, d, ps0); }
            if ((w0 >> bit1) & 1u) { se0 += e01; float d = s01 - 1.f; ps0 = fmaf(d, d, ps0); }
            if ((w1 >> bit0) & 1u) { se1 += e10; float d = s10 - 1.f; ps1 = fmaf(d, d, ps1); }
            if ((w1 >> bit1) & 1u) { se1 += e11; float d = s11 - 1.f; ps1 = fmaf(d, d, ps1); }
        }

        __syncthreads();   // all reads of Bs[buf] done
        if (ct + 2 < CT_PER) {
            const float* src = xb + (size_t)(c0 + (ct + 2) * 64) * Dd;
            #pragma unroll
            for (int t = 0; t < 4; t++)
                cpasync16(bsm[buf] + dsto + t * 16 * STR * 4, src + (size_t)(ldr + t * 16) * Dd + cg * 4);
            CP_COMMIT();
        }
    }

    // reduce over tg lanes (width 4), then atomically add row partials
    #pragma unroll
    for (int off = 2; off > 0; off >>= 1) {
        te0 += __shfl_down_sync(0xffffffffu, te0, off, 4);
        te1 += __shfl_down_sync(0xffffffffu, te1, off, 4);
        se0 += __shfl_down_sync(0xffffffffu, se0, off, 4);
        se1 += __shfl_down_sync(0xffffffffu, se1, off, 4);
        ps0 += __shfl_down_sync(0xffffffffu, ps0, off, 4);
        ps1 += __shfl_down_sync(0xffffffffu, ps1, off, 4);
    }
    if (tg == 0) {
        size_t o0 = (size_t)b * Nn + r0g;
        atomicAdd(&g_te[o0], te0);
        atomicAdd(&g_se[o0], se0);
        atomicAdd(&g_ps[o0], ps0);
        atomicAdd(&g_te[o0 + 8], te1);
        atomicAdd(&g_se[o0 + 8], se1);
        atomicAdd(&g_ps[o0 + 8], ps1);
    }
}

// ---------------- kernel 4: per-row log + per-instance fold ----------------
// 64 blocks x 256 threads; each block covers 256 rows of one batch.
__global__ void row_kernel() {
    __shared__ float s_lp[Ii];
    __shared__ float s_ln[Ii];
    int t = threadIdx.x;
    int idx = blockIdx.x * 256 + t;
    int b = idx >> 12;
    if (t < Ii) { s_lp[t] = 0.f; s_ln[t] = 0.f; }
    __syncthreads();
    int i = g_inst[idx];
    if (i >= 0) {
        atomicAdd(&s_lp[i], g_ps[idx]);
        float neg = g_te[idx] - g_se[idx];
        atomicAdd(&s_ln[i], logf(fmaxf(neg, 1e-30f)));
    }
    __syncthreads();
    if (t < Ii) {
        if (s_lp[t] != 0.f) atomicAdd(&g_lp[b * Ii + t], s_lp[t]);
        if (s_ln[t] != 0.f) atomicAdd(&g_ln[b * Ii + t], s_ln[t]);
    }
}

// ---------------- kernel 5: tiny finish ----------------
__global__ void final_kernel(float* out) {
    __shared__ float s_red[128];
    int t = threadIdx.x;
    float cnt = (float)g_cnt[t];
    float valid = (cnt >= 5.0f) ? 1.0f : 0.0f;
    float lp = g_lp[t] / fmaxf(cnt * cnt, 1.0f);
    float ln = g_ln[t] / fmaxf(cnt, 1.0f);
    s_red[t] = valid * (WP * lp + (1.0f - WP) * ln);
    __syncthreads();
    for (int off = 64; off > 0; off >>= 1) {
        if (t < off) s_red[t] += s_red[t + off];
        __syncthreads();
    }
    if (t == 0) out[0] = s_red[0] / (float)(Bb * Ii);
}

// ---------------- launch ----------------
extern "C" void kernel_launch(void* const* d_in, const int* in_sizes, int n_in,
                              void* d_out, int out_size) {
    const float* x   = (const float*)d_in[0];
    const void*  lab = d_in[1];
    float* out = (float*)d_out;

    detect_kernel<<<1, 256>>>((const unsigned int*)lab);
    inst_kernel<<<(Bb * Nn + 255) / 256, 256>>>(lab);
    cvt_kernel<<<512, 256>>>(x);
    sim_kernel<<<Bb * 32 * CQS, 256>>>();
    row_kernel<<<Bb * Nn / 256, 256>>>();
    final_kernel<<<1, 128>>>(out);
}